// round 9
// baseline (speedup 1.0000x reference)
#include <cuda_runtime.h>
#include <math.h>
#include <stdint.h>
#include <mma.h>

using namespace nvcuda;

// Problem constants
#define Sq   2048
#define Dm   512
#define NH   8
#define DKh  64
#define NB   2
#define FFd  2048
#define MROWS (NB*Sq)   // 4096

// ---------------- scratch (static device globals; no allocs) ----------------
__device__ float g_q  [MROWS*Dm];
__device__ float g_k  [MROWS*Dm];
__device__ float g_v  [MROWS*Dm];
__device__ float g_t0 [MROWS*Dm];
__device__ float g_t0b[MROWS*Dm];
__device__ float g_o1 [MROWS*Dm];
__device__ float g_o2 [MROWS*Dm];
__device__ float g_ffh[MROWS*FFd];
__device__ float g_part[(size_t)NB*NH*Sq*16];   // row partial sums (2MB)

// ---------------- cp.async helpers ------------------------------------------
__device__ __forceinline__ void cp16(const void* dst, const void* src) {
    uint32_t d = (uint32_t)__cvta_generic_to_shared(dst);
    asm volatile("cp.async.cg.shared.global [%0], [%1], 16;" :: "r"(d), "l"(src));
}
#define CP_COMMIT() asm volatile("cp.async.commit_group;" ::: "memory")
#define CP_WAIT1()  asm volatile("cp.async.wait_group 1;" ::: "memory")
#define CP_WAIT0()  asm volatile("cp.async.wait_group 0;" ::: "memory")

// =============== shared GEMM body: C = A[.,K] @ B[K,N] + bias ================
// BM=128, BN=128, BK=16, 3-stage cp.async, ONE sync per K-iter, 256 threads
__device__ __forceinline__ void gemm_body(
    const float* __restrict__ A, const float* __restrict__ B,
    const float* __restrict__ bias, float* __restrict__ C,
    int N, int K, int m0, int n0, bool relu, char* sm)
{
    float (*As)[128][24] = (float(*)[128][24])sm;                 // 3 x 12288
    float (*Bs)[16][136] = (float(*)[16][136])(sm + 36864);       // 3 x 8704
    float (*BiasS)[136]  = (float(*)[136])(sm + 62976);           // 8704

    const int t = threadIdx.x, wid = t >> 5;
    const int wm = (wid & 3) * 32, wn = (wid >> 2) * 64;

    {
        int col = t & 127, r0 = (t >> 7) * 8;
        float bv = bias[n0 + col];
#pragma unroll
        for (int r = 0; r < 8; r++) BiasS[r0 + r][col] = bv;
    }
    __syncthreads();

    wmma::fragment<wmma::accumulator, 16, 16, 8, float> acc[2][4];
#pragma unroll
    for (int i = 0; i < 2; i++)
#pragma unroll
        for (int j = 0; j < 4; j++)
            wmma::load_matrix_sync(acc[i][j], &BiasS[0][wn + j*16], 136,
                                   wmma::mem_row_major);

    const float* Ab = A + (size_t)m0 * K;
    const float* Bb = B + n0;

#define G_LOAD(st, k0)                                                    \
    {                                                                     \
        _Pragma("unroll")                                                 \
        for (int c = t; c < 512; c += 256) {                              \
            int row = c >> 2, sg = c & 3;                                 \
            cp16(&As[st][row][sg*4], Ab + (size_t)row * K + (k0) + sg*4); \
        }                                                                 \
        _Pragma("unroll")                                                 \
        for (int c = t; c < 512; c += 256) {                              \
            int row = c >> 5, sg = c & 31;                                \
            cp16(&Bs[st][row][sg*4], Bb + (size_t)((k0) + row) * N + sg*4); \
        }                                                                 \
        CP_COMMIT();                                                      \
    }

    G_LOAD(0, 0)
    G_LOAD(1, 16)

    const int KT = K >> 4;
    for (int kt = 0; kt < KT; kt++) {
        const int cur = kt % 3;
        if (kt + 1 < KT) CP_WAIT1(); else CP_WAIT0();
        __syncthreads();
        if (kt + 2 < KT) { int st = (kt + 2) % 3; G_LOAD(st, (kt + 2) << 4) }
#pragma unroll
        for (int ks = 0; ks < 16; ks += 8) {
            wmma::fragment<wmma::matrix_a, 16, 16, 8, wmma::precision::tf32,
                           wmma::row_major> af[2];
            wmma::fragment<wmma::matrix_b, 16, 16, 8, wmma::precision::tf32,
                           wmma::row_major> bf[4];
#pragma unroll
            for (int i = 0; i < 2; i++)
                wmma::load_matrix_sync(af[i], &As[cur][wm + i*16][ks], 24);
#pragma unroll
            for (int j = 0; j < 4; j++)
                wmma::load_matrix_sync(bf[j], &Bs[cur][ks][wn + j*16], 136);
#pragma unroll
            for (int i = 0; i < 2; i++)
#pragma unroll
                for (int j = 0; j < 4; j++)
                    wmma::mma_sync(acc[i][j], af[i], bf[j], acc[i][j]);
        }
    }
#undef G_LOAD

#pragma unroll
    for (int i = 0; i < 2; i++)
#pragma unroll
        for (int j = 0; j < 4; j++) {
            if (relu) {
#pragma unroll
                for (int e = 0; e < acc[i][j].num_elements; e++)
                    acc[i][j].x[e] = fmaxf(acc[i][j].x[e], 0.f);
            }
            wmma::store_matrix_sync(
                &C[(size_t)(m0 + wm + i*16) * N + n0 + wn + j*16],
                acc[i][j], N, wmma::mem_row_major);
        }
}

template<bool RELU>
__global__ void __launch_bounds__(256, 2) wm_gemm(
    const float* __restrict__ A, const float* __restrict__ B,
    const float* __restrict__ bias, float* __restrict__ C, int N, int K)
{
    extern __shared__ char sm[];
    gemm_body(A, B, bias, C, N, K, blockIdx.y * 128, blockIdx.x * 128, RELU, sm);
}

// fused triple GEMM (shares grid across 3 weight matrices, N=512 each)
__global__ void __launch_bounds__(256, 2) wm_gemm3(
    const float* __restrict__ A0, const float* __restrict__ A1,
    const float* __restrict__ A2,
    const float* __restrict__ B0, const float* __restrict__ B1,
    const float* __restrict__ B2,
    const float* __restrict__ b0, const float* __restrict__ b1,
    const float* __restrict__ b2,
    float* __restrict__ C0, float* __restrict__ C1, float* __restrict__ C2,
    int N, int K)
{
    extern __shared__ char sm[];
    const int mat = blockIdx.x >> 2;
    const float* A = (mat == 0) ? A0 : (mat == 1) ? A1 : A2;
    const float* B = (mat == 0) ? B0 : (mat == 1) ? B1 : B2;
    const float* bias = (mat == 0) ? b0 : (mat == 1) ? b1 : b2;
    float* C = (mat == 0) ? C0 : (mat == 1) ? C1 : C2;
    gemm_body(A, B, bias, C, N, K, blockIdx.y * 128, (blockIdx.x & 3) * 128,
              false, sm);
}

// =============== BM=64 GEMM for underfilled shapes (wo, ff2) ================
__global__ void __launch_bounds__(256, 2) wm_gemm64(
    const float* __restrict__ A, const float* __restrict__ B,
    const float* __restrict__ bias, float* __restrict__ C, int N, int K)
{
    extern __shared__ char sm[];
    float (*As)[64][24]  = (float(*)[64][24])sm;                  // 3 x 6144
    float (*Bs)[16][136] = (float(*)[16][136])(sm + 18432);       // 3 x 8704
    float (*BiasS)[136]  = (float(*)[136])(sm + 44544);           // 8704

    const int t = threadIdx.x, wid = t >> 5;
    const int m0 = blockIdx.y * 64, n0 = blockIdx.x * 128;
    const int wm = (wid & 3) * 16, wn = (wid >> 2) * 64;

    {
        int col = t & 127, r0 = (t >> 7) * 8;
        float bv = bias[n0 + col];
#pragma unroll
        for (int r = 0; r < 8; r++) BiasS[r0 + r][col] = bv;
    }
    __syncthreads();

    wmma::fragment<wmma::accumulator, 16, 16, 8, float> acc[4];
#pragma unroll
    for (int j = 0; j < 4; j++)
        wmma::load_matrix_sync(acc[j], &BiasS[0][wn + j*16], 136,
                               wmma::mem_row_major);

    const float* Ab = A + (size_t)m0 * K;
    const float* Bb = B + n0;

#define G64_LOAD(st, k0)                                                  \
    {                                                                     \
        int row = t >> 2, sg = t & 3;                                     \
        cp16(&As[st][row][sg*4], Ab + (size_t)row * K + (k0) + sg*4);     \
        _Pragma("unroll")                                                 \
        for (int c = t; c < 512; c += 256) {                              \
            int r2 = c >> 5, s2 = c & 31;                                 \
            cp16(&Bs[st][r2][s2*4], Bb + (size_t)((k0) + r2) * N + s2*4); \
        }                                                                 \
        CP_COMMIT();                                                      \
    }

    G64_LOAD(0, 0)
    G64_LOAD(1, 16)

    const int KT = K >> 4;
    for (int kt = 0; kt < KT; kt++) {
        const int cur = kt % 3;
        if (kt + 1 < KT) CP_WAIT1(); else CP_WAIT0();
        __syncthreads();
        if (kt + 2 < KT) { int st = (kt + 2) % 3; G64_LOAD(st, (kt + 2) << 4) }
#pragma unroll
        for (int ks = 0; ks < 16; ks += 8) {
            wmma::fragment<wmma::matrix_a, 16, 16, 8, wmma::precision::tf32,
                           wmma::row_major> af;
            wmma::fragment<wmma::matrix_b, 16, 16, 8, wmma::precision::tf32,
                           wmma::row_major> bf[4];
            wmma::load_matrix_sync(af, &As[cur][wm][ks], 24);
#pragma unroll
            for (int j = 0; j < 4; j++)
                wmma::load_matrix_sync(bf[j], &Bs[cur][ks][wn + j*16], 136);
#pragma unroll
            for (int j = 0; j < 4; j++)
                wmma::mma_sync(acc[j], af, bf[j], acc[j]);
        }
    }
#undef G64_LOAD

#pragma unroll
    for (int j = 0; j < 4; j++)
        wmma::store_matrix_sync(&C[(size_t)(m0 + wm) * N + n0 + wn + j*16],
                                acc[j], N, wmma::mem_row_major);
}

// ===== logits+exp: E = exp(scale*Q@K^T) (masked->0) + row partial sums ======
__global__ void __launch_bounds__(256, 2) wm_logits_exp(
    const float* __restrict__ Q, const float* __restrict__ Km,
    float* __restrict__ out, float* __restrict__ part, int causal)
{
    extern __shared__ char smc[];
    float (*Qs)[68] = (float(*)[68])smc;                 // 34816
    float (*Ks)[68] = (float(*)[68])(smc + 34816);       // 34816
    float (*St)[136] = (float(*)[136])smc;               // reuse: 69632

    const int bh = blockIdx.z;
    const int b = bh >> 3, h = bh & 7;
    const int i0 = blockIdx.y * 128, j0 = blockIdx.x * 128;
    const int jt = blockIdx.x;
    const int t = threadIdx.x, wid = t >> 5, lane = t & 31;
    float* Ob = out + (size_t)bh * Sq * Sq;

    if (causal && j0 > i0 + 127) {
        const float4 zero = make_float4(0.f, 0.f, 0.f, 0.f);
        for (int idx = t; idx < 4096; idx += 256) {
            int row = idx >> 5, c4 = idx & 31;
            *(float4*)&Ob[(size_t)(i0 + row) * Sq + j0 + c4 * 4] = zero;
        }
        if (t < 128)
            part[((size_t)bh * Sq + i0 + t) * 16 + jt] = 0.f;
        return;
    }

    const float* Qb = Q  + (size_t)b * Sq * Dm + h * DKh + (size_t)i0 * Dm;
    const float* Kb = Km + (size_t)b * Sq * Dm + h * DKh + (size_t)j0 * Dm;

#pragma unroll
    for (int c = t; c < 2048; c += 256) {
        int row = c >> 4, sg = c & 15;
        cp16(&Qs[row][sg*4], Qb + (size_t)row * Dm + sg*4);
    }
#pragma unroll
    for (int c = t; c < 2048; c += 256) {
        int row = c >> 4, sg = c & 15;
        cp16(&Ks[row][sg*4], Kb + (size_t)row * Dm + sg*4);
    }
    CP_COMMIT();
    CP_WAIT0();
    __syncthreads();

    const int wm = (wid & 3) * 32, wn = (wid >> 2) * 64;
    wmma::fragment<wmma::accumulator, 16, 16, 8, float> acc[2][4];
#pragma unroll
    for (int i = 0; i < 2; i++)
#pragma unroll
        for (int j = 0; j < 4; j++) wmma::fill_fragment(acc[i][j], 0.f);

#pragma unroll
    for (int ks = 0; ks < 64; ks += 8) {
        wmma::fragment<wmma::matrix_a, 16, 16, 8, wmma::precision::tf32,
                       wmma::row_major> af[2];
        wmma::fragment<wmma::matrix_b, 16, 16, 8, wmma::precision::tf32,
                       wmma::col_major> bf[4];
#pragma unroll
        for (int i = 0; i < 2; i++)
            wmma::load_matrix_sync(af[i], &Qs[wm + i*16][ks], 68);
#pragma unroll
        for (int j = 0; j < 4; j++)
            wmma::load_matrix_sync(bf[j], &Ks[wn + j*16][ks], 68);
#pragma unroll
        for (int i = 0; i < 2; i++)
#pragma unroll
            for (int j = 0; j < 4; j++)
                wmma::mma_sync(acc[i][j], af[i], bf[j], acc[i][j]);
    }
    __syncthreads();   // done with Qs/Ks; reuse as staging

#pragma unroll
    for (int i = 0; i < 2; i++)
#pragma unroll
        for (int j = 0; j < 4; j++)
            wmma::store_matrix_sync(&St[wm + i*16][wn + j*16], acc[i][j], 136,
                                    wmma::mem_row_major);
    __syncthreads();

    // epilogue: warp-per-row, fully coalesced 512B writes
    const int gjl = j0 + lane * 4;
#pragma unroll
    for (int r = 0; r < 16; r++) {
        const int row = wid * 16 + r;
        const int gi = i0 + row;
        float4 v = *(float4*)&St[row][lane * 4];
        v.x = (causal && gjl + 0 > gi) ? 0.f : __expf(v.x * 0.125f);
        v.y = (causal && gjl + 1 > gi) ? 0.f : __expf(v.y * 0.125f);
        v.z = (causal && gjl + 2 > gi) ? 0.f : __expf(v.z * 0.125f);
        v.w = (causal && gjl + 3 > gi) ? 0.f : __expf(v.w * 0.125f);
        float psum = v.x + v.y + v.z + v.w;
#pragma unroll
        for (int o = 16; o; o >>= 1)
            psum += __shfl_xor_sync(0xffffffffu, psum, o);
        *(float4*)&Ob[(size_t)gi * Sq + j0 + lane * 4] = v;
        if (lane == 0)
            part[((size_t)bh * Sq + gi) * 16 + jt] = psum;
    }
}

// ===== AV: MMA on raw E; writes aw = E/sum during load; scales out by 1/sum =
// 3-stage cp.async, one sync per iter; optional split-K via gridDim.z
__global__ void __launch_bounds__(256, 2) wm_av_norm(
    float* __restrict__ aw, const float* __restrict__ V,
    const float* __restrict__ part, float* __restrict__ outA,
    float* __restrict__ outB, int causal)
{
    extern __shared__ char sm[];
    float (*As)[128][24] = (float(*)[128][24])sm;            // 3 x 12288
    float (*Bs)[16][72]  = (float(*)[16][72])(sm + 36864);   // 3 x 4608
    float* invs          = (float*)(sm + 50688);             // 512
    float (*Os)[72]      = (float(*)[72])sm;                 // reuse: 36864

    const int bh = blockIdx.y;
    const int b = bh >> 3, h = bh & 7;
    const int i0 = blockIdx.x * 128;
    const int ks = blockIdx.z;
    const int t = threadIdx.x, wid = t >> 5, lane = t & 31;

    float* out = (ks == 0) ? outA : outB;
    float*       Abw = aw + (size_t)bh * Sq * Sq + (size_t)i0 * Sq;
    const float* Bb  = V + (size_t)b * Sq * Dm + h * DKh;
    float*       Cb  = out + (size_t)b * Sq * Dm + h * DKh;

    const int ktPer = 128 / gridDim.z;
    const int kt_lo = ks * ktPer;
    int kt_hi = kt_lo + ktPer;
    if (causal) { int ce = (i0 >> 4) + 8; if (ce < kt_hi) kt_hi = ce; }

    if (kt_hi <= kt_lo) {
        // no work: zero partial output region
        const float4 zero = make_float4(0.f, 0.f, 0.f, 0.f);
        for (int idx = t; idx < 2048; idx += 256) {
            int row = idx >> 4, c4 = idx & 15;
            *(float4*)&Cb[(size_t)(i0 + row) * Dm + c4 * 4] = zero;
        }
        return;
    }

    // per-row inverse softmax sums
    if (t < 128) {
        const float* pp = part + ((size_t)bh * Sq + i0 + t) * 16;
        float s = 0.f;
#pragma unroll
        for (int jt = 0; jt < 16; jt++) s += pp[jt];
        invs[t] = 1.f / s;
    }

    const int wm = (wid & 3) * 32, wn = (wid >> 2) * 32;
    wmma::fragment<wmma::accumulator, 16, 16, 8, float> acc[2][2];
#pragma unroll
    for (int i = 0; i < 2; i++)
#pragma unroll
        for (int j = 0; j < 2; j++) wmma::fill_fragment(acc[i][j], 0.f);

#define AV_LOAD(st, kt)                                                   \
    {                                                                     \
        _Pragma("unroll")                                                 \
        for (int c = t; c < 512; c += 256) {                              \
            int row = c >> 2, sg = c & 3;                                 \
            cp16(&As[st][row][sg*4],                                      \
                 Abw + (size_t)row * Sq + ((kt) << 4) + sg*4);            \
        }                                                                 \
        {                                                                 \
            int row = t >> 4, sg = t & 15;                                \
            cp16(&Bs[st][row][sg*4],                                      \
                 Bb + (size_t)(((kt) << 4) + row) * Dm + sg*4);           \
        }                                                                 \
        CP_COMMIT();                                                      \
    }

    AV_LOAD(0, kt_lo)
    if (kt_lo + 1 < kt_hi) AV_LOAD(1, kt_lo + 1)

    for (int kt = kt_lo; kt < kt_hi; kt++) {
        const int cur = (kt - kt_lo) % 3;
        if (kt + 1 < kt_hi) CP_WAIT1(); else CP_WAIT0();
        __syncthreads();
        if (kt + 2 < kt_hi) {
            int st = (kt - kt_lo + 2) % 3;
            AV_LOAD(st, kt + 2)
        }

        // write final normalized aw for this K-tile (reads raw E from smem)
        {
            int row = t >> 1, c0 = (t & 1) * 8;
            float inv = invs[row];
            float4 a0 = *(float4*)&As[cur][row][c0];
            float4 a1 = *(float4*)&As[cur][row][c0 + 4];
            a0.x *= inv; a0.y *= inv; a0.z *= inv; a0.w *= inv;
            a1.x *= inv; a1.y *= inv; a1.z *= inv; a1.w *= inv;
            float* aww = Abw + (size_t)row * Sq + (kt << 4) + c0;
            *(float4*)aww       = a0;
            *(float4*)(aww + 4) = a1;
        }

#pragma unroll
        for (int ksn = 0; ksn < 16; ksn += 8) {
            wmma::fragment<wmma::matrix_a, 16, 16, 8, wmma::precision::tf32,
                           wmma::row_major> af[2];
            wmma::fragment<wmma::matrix_b, 16, 16, 8, wmma::precision::tf32,
                           wmma::row_major> bf[2];
#pragma unroll
            for (int i = 0; i < 2; i++)
                wmma::load_matrix_sync(af[i], &As[cur][wm + i*16][ksn], 24);
#pragma unroll
            for (int j = 0; j < 2; j++)
                wmma::load_matrix_sync(bf[j], &Bs[cur][ksn][wn + j*16], 72);
#pragma unroll
            for (int i = 0; i < 2; i++)
#pragma unroll
                for (int j = 0; j < 2; j++)
                    wmma::mma_sync(acc[i][j], af[i], bf[j], acc[i][j]);
        }
    }
#undef AV_LOAD

    // epilogue: stage raw acc, then scale rows by 1/sum, coalesced write
    __syncthreads();
#pragma unroll
    for (int i = 0; i < 2; i++)
#pragma unroll
        for (int j = 0; j < 2; j++)
            wmma::store_matrix_sync(&Os[wm + i*16][wn + j*16], acc[i][j], 72,
                                    wmma::mem_row_major);
    __syncthreads();
#pragma unroll
    for (int r = 0; r < 16; r++) {
        const int row = wid * 16 + r;
        float2 v = *(float2*)&Os[row][lane * 2];
        const float inv = invs[row];
        v.x *= inv; v.y *= inv;
        *(float2*)&Cb[(size_t)(i0 + row) * Dm + lane * 2] = v;
    }
}

// ---------------- elementwise add (for split-K partials) --------------------
__global__ void __launch_bounds__(256) add2(
    float* __restrict__ a, const float* __restrict__ b)
{
    const size_t i = ((size_t)blockIdx.x * 256 + threadIdx.x) * 4;
    float4 va = *(float4*)&a[i];
    float4 vb = *(const float4*)&b[i];
    va.x += vb.x; va.y += vb.y; va.z += vb.z; va.w += vb.w;
    *(float4*)&a[i] = va;
}

// ---------------- residual add + layernorm over last dim (512) --------------
__global__ void __launch_bounds__(128) add_ln(
    const float* __restrict__ a, const float* __restrict__ r,
    const float* __restrict__ g, const float* __restrict__ be,
    float* __restrict__ out)
{
    const size_t row = blockIdx.x;
    const int t = threadIdx.x;
    __shared__ float red[4];

    float4 va = *(const float4*)&a[row * Dm + t*4];
    float4 vr = *(const float4*)&r[row * Dm + t*4];
    float x0 = va.x + vr.x, x1 = va.y + vr.y, x2 = va.z + vr.z, x3 = va.w + vr.w;

    float s = x0 + x1 + x2 + x3;
#pragma unroll
    for (int o = 16; o; o >>= 1) s += __shfl_xor_sync(0xffffffffu, s, o);
    if ((t & 31) == 0) red[t >> 5] = s;
    __syncthreads();
    float mean = (red[0] + red[1] + red[2] + red[3]) * (1.f / 512.f);

    float d0 = x0 - mean, d1 = x1 - mean, d2 = x2 - mean, d3 = x3 - mean;
    float vs = d0*d0 + d1*d1 + d2*d2 + d3*d3;
#pragma unroll
    for (int o = 16; o; o >>= 1) vs += __shfl_xor_sync(0xffffffffu, vs, o);
    __syncthreads();
    if ((t & 31) == 0) red[t >> 5] = vs;
    __syncthreads();
    float var = (red[0] + red[1] + red[2] + red[3]) * (1.f / 512.f);
    float rstd = rsqrtf(var + 1e-6f);

    float4 vg = *(const float4*)&g[t*4];
    float4 vb = *(const float4*)&be[t*4];
    float4 o4;
    o4.x = d0 * rstd * vg.x + vb.x;
    o4.y = d1 * rstd * vg.y + vb.y;
    o4.z = d2 * rstd * vg.z + vb.z;
    o4.w = d3 * rstd * vg.w + vb.w;
    *(float4*)&out[row * Dm + t*4] = o4;
}

// ---------------- launch ----------------------------------------------------
extern "C" void kernel_launch(void* const* d_in, const int* in_sizes, int n_in,
                              void* d_out, int out_size)
{
    const float* x    = (const float*)d_in[0];
    const float* enc  = (const float*)d_in[1];
    const float* wq1 = (const float*)d_in[3],  *bq1 = (const float*)d_in[4];
    const float* wk1 = (const float*)d_in[5],  *bk1 = (const float*)d_in[6];
    const float* wv1 = (const float*)d_in[7],  *bv1 = (const float*)d_in[8];
    const float* wo1 = (const float*)d_in[9],  *bo1 = (const float*)d_in[10];
    const float* wq2 = (const float*)d_in[11], *bq2 = (const float*)d_in[12];
    const float* wk2 = (const float*)d_in[13], *bk2 = (const float*)d_in[14];
    const float* wv2 = (const float*)d_in[15], *bv2 = (const float*)d_in[16];
    const float* wo2 = (const float*)d_in[17], *bo2 = (const float*)d_in[18];
    const float* wf1 = (const float*)d_in[19], *bf1 = (const float*)d_in[20];
    const float* wf2 = (const float*)d_in[21], *bf2 = (const float*)d_in[22];
    const float* g1 = (const float*)d_in[23], *be1 = (const float*)d_in[24];
    const float* g2 = (const float*)d_in[25], *be2 = (const float*)d_in[26];
    const float* g3 = (const float*)d_in[27], *be3 = (const float*)d_in[28];

    float* out3 = (float*)d_out;
    float* aw1  = out3 + (size_t)NB * Sq * Dm;
    float* aw2  = aw1  + (size_t)NB * NH * Sq * Sq;

    float *q, *k, *v, *t0, *t0b, *o1, *o2, *ffh, *part;
    cudaGetSymbolAddress((void**)&q,    g_q);
    cudaGetSymbolAddress((void**)&k,    g_k);
    cudaGetSymbolAddress((void**)&v,    g_v);
    cudaGetSymbolAddress((void**)&t0,   g_t0);
    cudaGetSymbolAddress((void**)&t0b,  g_t0b);
    cudaGetSymbolAddress((void**)&o1,   g_o1);
    cudaGetSymbolAddress((void**)&o2,   g_o2);
    cudaGetSymbolAddress((void**)&ffh,  g_ffh);
    cudaGetSymbolAddress((void**)&part, g_part);

    const int SMEM_GEMM  = 71680;
    const int SMEM_G64   = 53248;
    const int SMEM_LOG   = 69632;
    const int SMEM_AV    = 51200;
    cudaFuncSetAttribute(wm_gemm<false>, cudaFuncAttributeMaxDynamicSharedMemorySize, SMEM_GEMM);
    cudaFuncSetAttribute(wm_gemm<true>,  cudaFuncAttributeMaxDynamicSharedMemorySize, SMEM_GEMM);
    cudaFuncSetAttribute(wm_gemm3,       cudaFuncAttributeMaxDynamicSharedMemorySize, SMEM_GEMM);
    cudaFuncSetAttribute(wm_gemm64,      cudaFuncAttributeMaxDynamicSharedMemorySize, SMEM_G64);
    cudaFuncSetAttribute(wm_logits_exp,  cudaFuncAttributeMaxDynamicSharedMemorySize, SMEM_LOG);
    cudaFuncSetAttribute(wm_av_norm,     cudaFuncAttributeMaxDynamicSharedMemorySize, SMEM_AV);

    const dim3 gProj64(Dm / 128, MROWS / 64);       // (4, 64)
    const dim3 gQKV(12, MROWS / 128);               // (12, 32)
    const dim3 gFF1(FFd / 128, MROWS / 128);        // (16, 32)
    const dim3 gLog(Sq / 128, Sq / 128, NB * NH);   // (16, 16, 16)
    const dim3 gAV1(Sq / 128, NB * NH, 2);          // split-K causal
    const dim3 gAV2(Sq / 128, NB * NH, 1);
    const int  nAdd = (MROWS * Dm) / 4 / 256;       // 2048

    // ---- self attention ----
    wm_gemm3<<<gQKV, 256, SMEM_GEMM>>>(x, x, x, wq1, wk1, wv1,
                                       bq1, bk1, bv1, q, k, v, Dm, Dm);
    wm_logits_exp<<<gLog, 256, SMEM_LOG>>>(q, k, aw1, part, 1);
    wm_av_norm<<<gAV1, 256, SMEM_AV>>>(aw1, v, part, t0, t0b, 1);
    add2<<<nAdd, 256>>>(t0, t0b);
    wm_gemm64<<<gProj64, 256, SMEM_G64>>>(t0, wo1, bo1, q, Dm, Dm);
    add_ln<<<MROWS, 128>>>(q, x, g1, be1, o1);

    // ---- cross attention ----
    wm_gemm3<<<gQKV, 256, SMEM_GEMM>>>(o1, enc, enc, wq2, wk2, wv2,
                                       bq2, bk2, bv2, q, k, v, Dm, Dm);
    wm_logits_exp<<<gLog, 256, SMEM_LOG>>>(q, k, aw2, part, 0);
    wm_av_norm<<<gAV2, 256, SMEM_AV>>>(aw2, v, part, t0, t0b, 0);
    wm_gemm64<<<gProj64, 256, SMEM_G64>>>(t0, wo2, bo2, q, Dm, Dm);
    add_ln<<<MROWS, 128>>>(q, o1, g2, be2, o2);

    // ---- FFN ----
    wm_gemm<true ><<<gFF1, 256, SMEM_GEMM>>>(o2, wf1, bf1, ffh, FFd, Dm);
    wm_gemm64<<<gProj64, 256, SMEM_G64>>>(ffh, wf2, bf2, t0, Dm, FFd);
    add_ln<<<MROWS, 128>>>(t0, o2, g3, be3, out3);
}

// round 10
// speedup vs baseline: 1.0020x; 1.0020x over previous
#include <cuda_runtime.h>
#include <math.h>
#include <stdint.h>
#include <mma.h>

using namespace nvcuda;

// Problem constants
#define Sq   2048
#define Dm   512
#define NH   8
#define DKh  64
#define NB   2
#define FFd  2048
#define MROWS (NB*Sq)   // 4096

// ---------------- scratch (static device globals; no allocs) ----------------
__device__ float g_q  [MROWS*Dm];
__device__ float g_k  [MROWS*Dm];
__device__ float g_v  [MROWS*Dm];
__device__ float g_t0 [MROWS*Dm];
__device__ float g_t0b[MROWS*Dm];
__device__ float g_o1 [MROWS*Dm];
__device__ float g_o2 [MROWS*Dm];
__device__ float g_ffh[MROWS*FFd];
__device__ float g_part[(size_t)NB*NH*Sq*16];   // row partial sums (2MB)

// ---------------- cp.async helpers ------------------------------------------
__device__ __forceinline__ void cp16(const void* dst, const void* src) {
    uint32_t d = (uint32_t)__cvta_generic_to_shared(dst);
    asm volatile("cp.async.cg.shared.global [%0], [%1], 16;" :: "r"(d), "l"(src));
}
#define CP_COMMIT() asm volatile("cp.async.commit_group;" ::: "memory")
#define CP_WAIT1()  asm volatile("cp.async.wait_group 1;" ::: "memory")
#define CP_WAIT0()  asm volatile("cp.async.wait_group 0;" ::: "memory")

// =============== shared GEMM body: C = A[.,K] @ B[K,N] + bias ================
// BM=128, BN=128, BK=16, 3-stage cp.async, ONE sync per K-iter, 256 threads
__device__ __forceinline__ void gemm_body(
    const float* __restrict__ A, const float* __restrict__ B,
    const float* __restrict__ bias, float* __restrict__ C,
    int N, int K, int m0, int n0, bool relu, char* sm)
{
    float (*As)[128][24] = (float(*)[128][24])sm;                 // 3 x 12288
    float (*Bs)[16][136] = (float(*)[16][136])(sm + 36864);       // 3 x 8704
    float (*BiasS)[136]  = (float(*)[136])(sm + 62976);           // 8704

    const int t = threadIdx.x, wid = t >> 5;
    const int wm = (wid & 3) * 32, wn = (wid >> 2) * 64;

    {
        int col = t & 127, r0 = (t >> 7) * 8;
        float bv = bias[n0 + col];
#pragma unroll
        for (int r = 0; r < 8; r++) BiasS[r0 + r][col] = bv;
    }
    __syncthreads();

    wmma::fragment<wmma::accumulator, 16, 16, 8, float> acc[2][4];
#pragma unroll
    for (int i = 0; i < 2; i++)
#pragma unroll
        for (int j = 0; j < 4; j++)
            wmma::load_matrix_sync(acc[i][j], &BiasS[0][wn + j*16], 136,
                                   wmma::mem_row_major);

    const float* Ab = A + (size_t)m0 * K;
    const float* Bb = B + n0;

#define G_LOAD(st, k0)                                                    \
    {                                                                     \
        _Pragma("unroll")                                                 \
        for (int c = t; c < 512; c += 256) {                              \
            int row = c >> 2, sg = c & 3;                                 \
            cp16(&As[st][row][sg*4], Ab + (size_t)row * K + (k0) + sg*4); \
        }                                                                 \
        _Pragma("unroll")                                                 \
        for (int c = t; c < 512; c += 256) {                              \
            int row = c >> 5, sg = c & 31;                                \
            cp16(&Bs[st][row][sg*4], Bb + (size_t)((k0) + row) * N + sg*4); \
        }                                                                 \
        CP_COMMIT();                                                      \
    }

    G_LOAD(0, 0)
    G_LOAD(1, 16)

    const int KT = K >> 4;
    for (int kt = 0; kt < KT; kt++) {
        const int cur = kt % 3;
        if (kt + 1 < KT) CP_WAIT1(); else CP_WAIT0();
        __syncthreads();
        if (kt + 2 < KT) { int st = (kt + 2) % 3; G_LOAD(st, (kt + 2) << 4) }
#pragma unroll
        for (int ks = 0; ks < 16; ks += 8) {
            wmma::fragment<wmma::matrix_a, 16, 16, 8, wmma::precision::tf32,
                           wmma::row_major> af[2];
            wmma::fragment<wmma::matrix_b, 16, 16, 8, wmma::precision::tf32,
                           wmma::row_major> bf[4];
#pragma unroll
            for (int i = 0; i < 2; i++)
                wmma::load_matrix_sync(af[i], &As[cur][wm + i*16][ks], 24);
#pragma unroll
            for (int j = 0; j < 4; j++)
                wmma::load_matrix_sync(bf[j], &Bs[cur][ks][wn + j*16], 136);
#pragma unroll
            for (int i = 0; i < 2; i++)
#pragma unroll
                for (int j = 0; j < 4; j++)
                    wmma::mma_sync(acc[i][j], af[i], bf[j], acc[i][j]);
        }
    }
#undef G_LOAD

#pragma unroll
    for (int i = 0; i < 2; i++)
#pragma unroll
        for (int j = 0; j < 4; j++) {
            if (relu) {
#pragma unroll
                for (int e = 0; e < acc[i][j].num_elements; e++)
                    acc[i][j].x[e] = fmaxf(acc[i][j].x[e], 0.f);
            }
            wmma::store_matrix_sync(
                &C[(size_t)(m0 + wm + i*16) * N + n0 + wn + j*16],
                acc[i][j], N, wmma::mem_row_major);
        }
}

template<bool RELU>
__global__ void __launch_bounds__(256, 2) wm_gemm(
    const float* __restrict__ A, const float* __restrict__ B,
    const float* __restrict__ bias, float* __restrict__ C, int N, int K)
{
    extern __shared__ char sm[];
    gemm_body(A, B, bias, C, N, K, blockIdx.y * 128, blockIdx.x * 128, RELU, sm);
}

// fused triple GEMM (shares grid across 3 weight matrices, N=512 each)
__global__ void __launch_bounds__(256, 2) wm_gemm3(
    const float* __restrict__ A0, const float* __restrict__ A1,
    const float* __restrict__ A2,
    const float* __restrict__ B0, const float* __restrict__ B1,
    const float* __restrict__ B2,
    const float* __restrict__ b0, const float* __restrict__ b1,
    const float* __restrict__ b2,
    float* __restrict__ C0, float* __restrict__ C1, float* __restrict__ C2,
    int N, int K)
{
    extern __shared__ char sm[];
    const int mat = blockIdx.x >> 2;
    const float* A = (mat == 0) ? A0 : (mat == 1) ? A1 : A2;
    const float* B = (mat == 0) ? B0 : (mat == 1) ? B1 : B2;
    const float* bias = (mat == 0) ? b0 : (mat == 1) ? b1 : b2;
    float* C = (mat == 0) ? C0 : (mat == 1) ? C1 : C2;
    gemm_body(A, B, bias, C, N, K, blockIdx.y * 128, (blockIdx.x & 3) * 128,
              false, sm);
}

// =============== BM=64 GEMM for underfilled shapes (wo, ff2) ================
__global__ void __launch_bounds__(256, 2) wm_gemm64(
    const float* __restrict__ A, const float* __restrict__ B,
    const float* __restrict__ bias, float* __restrict__ C, int N, int K)
{
    extern __shared__ char sm[];
    float (*As)[64][24]  = (float(*)[64][24])sm;                  // 3 x 6144
    float (*Bs)[16][136] = (float(*)[16][136])(sm + 18432);       // 3 x 8704
    float (*BiasS)[136]  = (float(*)[136])(sm + 44544);           // 8704

    const int t = threadIdx.x, wid = t >> 5;
    const int m0 = blockIdx.y * 64, n0 = blockIdx.x * 128;
    const int wm = (wid & 3) * 16, wn = (wid >> 2) * 64;

    {
        int col = t & 127, r0 = (t >> 7) * 8;
        float bv = bias[n0 + col];
#pragma unroll
        for (int r = 0; r < 8; r++) BiasS[r0 + r][col] = bv;
    }
    __syncthreads();

    wmma::fragment<wmma::accumulator, 16, 16, 8, float> acc[4];
#pragma unroll
    for (int j = 0; j < 4; j++)
        wmma::load_matrix_sync(acc[j], &BiasS[0][wn + j*16], 136,
                               wmma::mem_row_major);

    const float* Ab = A + (size_t)m0 * K;
    const float* Bb = B + n0;

#define G64_LOAD(st, k0)                                                  \
    {                                                                     \
        int row = t >> 2, sg = t & 3;                                     \
        cp16(&As[st][row][sg*4], Ab + (size_t)row * K + (k0) + sg*4);     \
        _Pragma("unroll")                                                 \
        for (int c = t; c < 512; c += 256) {                              \
            int r2 = c >> 5, s2 = c & 31;                                 \
            cp16(&Bs[st][r2][s2*4], Bb + (size_t)((k0) + r2) * N + s2*4); \
        }                                                                 \
        CP_COMMIT();                                                      \
    }

    G64_LOAD(0, 0)
    G64_LOAD(1, 16)

    const int KT = K >> 4;
    for (int kt = 0; kt < KT; kt++) {
        const int cur = kt % 3;
        if (kt + 1 < KT) CP_WAIT1(); else CP_WAIT0();
        __syncthreads();
        if (kt + 2 < KT) { int st = (kt + 2) % 3; G64_LOAD(st, (kt + 2) << 4) }
#pragma unroll
        for (int ks = 0; ks < 16; ks += 8) {
            wmma::fragment<wmma::matrix_a, 16, 16, 8, wmma::precision::tf32,
                           wmma::row_major> af;
            wmma::fragment<wmma::matrix_b, 16, 16, 8, wmma::precision::tf32,
                           wmma::row_major> bf[4];
            wmma::load_matrix_sync(af, &As[cur][wm][ks], 24);
#pragma unroll
            for (int j = 0; j < 4; j++)
                wmma::load_matrix_sync(bf[j], &Bs[cur][ks][wn + j*16], 136);
#pragma unroll
            for (int j = 0; j < 4; j++)
                wmma::mma_sync(acc[j], af, bf[j], acc[j]);
        }
    }
#undef G64_LOAD

#pragma unroll
    for (int j = 0; j < 4; j++)
        wmma::store_matrix_sync(&C[(size_t)(m0 + wm) * N + n0 + wn + j*16],
                                acc[j], N, wmma::mem_row_major);
}

// ===== logits+exp: E = exp(scale*Q@K^T) (masked->0) + row partial sums ======
__global__ void __launch_bounds__(256, 2) wm_logits_exp(
    const float* __restrict__ Q, const float* __restrict__ Km,
    float* __restrict__ out, float* __restrict__ part, int causal)
{
    extern __shared__ char smc[];
    float (*Qs)[68] = (float(*)[68])smc;                 // 34816
    float (*Ks)[68] = (float(*)[68])(smc + 34816);       // 34816
    float (*St)[136] = (float(*)[136])smc;               // reuse: 69632

    const int bh = blockIdx.z;
    const int b = bh >> 3, h = bh & 7;
    const int i0 = blockIdx.y * 128, j0 = blockIdx.x * 128;
    const int jt = blockIdx.x;
    const int t = threadIdx.x, wid = t >> 5, lane = t & 31;
    float* Ob = out + (size_t)bh * Sq * Sq;

    if (causal && j0 > i0 + 127) {
        const float4 zero = make_float4(0.f, 0.f, 0.f, 0.f);
        for (int idx = t; idx < 4096; idx += 256) {
            int row = idx >> 5, c4 = idx & 31;
            *(float4*)&Ob[(size_t)(i0 + row) * Sq + j0 + c4 * 4] = zero;
        }
        if (t < 128)
            part[((size_t)bh * Sq + i0 + t) * 16 + jt] = 0.f;
        return;
    }

    const float* Qb = Q  + (size_t)b * Sq * Dm + h * DKh + (size_t)i0 * Dm;
    const float* Kb = Km + (size_t)b * Sq * Dm + h * DKh + (size_t)j0 * Dm;

#pragma unroll
    for (int c = t; c < 2048; c += 256) {
        int row = c >> 4, sg = c & 15;
        cp16(&Qs[row][sg*4], Qb + (size_t)row * Dm + sg*4);
    }
#pragma unroll
    for (int c = t; c < 2048; c += 256) {
        int row = c >> 4, sg = c & 15;
        cp16(&Ks[row][sg*4], Kb + (size_t)row * Dm + sg*4);
    }
    CP_COMMIT();
    CP_WAIT0();
    __syncthreads();

    const int wm = (wid & 3) * 32, wn = (wid >> 2) * 64;
    wmma::fragment<wmma::accumulator, 16, 16, 8, float> acc[2][4];
#pragma unroll
    for (int i = 0; i < 2; i++)
#pragma unroll
        for (int j = 0; j < 4; j++) wmma::fill_fragment(acc[i][j], 0.f);

#pragma unroll
    for (int ks = 0; ks < 64; ks += 8) {
        wmma::fragment<wmma::matrix_a, 16, 16, 8, wmma::precision::tf32,
                       wmma::row_major> af[2];
        wmma::fragment<wmma::matrix_b, 16, 16, 8, wmma::precision::tf32,
                       wmma::col_major> bf[4];
#pragma unroll
        for (int i = 0; i < 2; i++)
            wmma::load_matrix_sync(af[i], &Qs[wm + i*16][ks], 68);
#pragma unroll
        for (int j = 0; j < 4; j++)
            wmma::load_matrix_sync(bf[j], &Ks[wn + j*16][ks], 68);
#pragma unroll
        for (int i = 0; i < 2; i++)
#pragma unroll
            for (int j = 0; j < 4; j++)
                wmma::mma_sync(acc[i][j], af[i], bf[j], acc[i][j]);
    }
    __syncthreads();   // done with Qs/Ks; reuse as staging

#pragma unroll
    for (int i = 0; i < 2; i++)
#pragma unroll
        for (int j = 0; j < 4; j++)
            wmma::store_matrix_sync(&St[wm + i*16][wn + j*16], acc[i][j], 136,
                                    wmma::mem_row_major);
    __syncthreads();

    // epilogue: warp-per-row, fully coalesced 512B writes
    const int gjl = j0 + lane * 4;
#pragma unroll
    for (int r = 0; r < 16; r++) {
        const int row = wid * 16 + r;
        const int gi = i0 + row;
        float4 v = *(float4*)&St[row][lane * 4];
        v.x = (causal && gjl + 0 > gi) ? 0.f : __expf(v.x * 0.125f);
        v.y = (causal && gjl + 1 > gi) ? 0.f : __expf(v.y * 0.125f);
        v.z = (causal && gjl + 2 > gi) ? 0.f : __expf(v.z * 0.125f);
        v.w = (causal && gjl + 3 > gi) ? 0.f : __expf(v.w * 0.125f);
        float psum = v.x + v.y + v.z + v.w;
#pragma unroll
        for (int o = 16; o; o >>= 1)
            psum += __shfl_xor_sync(0xffffffffu, psum, o);
        *(float4*)&Ob[(size_t)gi * Sq + j0 + lane * 4] = v;
        if (lane == 0)
            part[((size_t)bh * Sq + gi) * 16 + jt] = psum;
    }
}

// ===== AV: MMA on raw E; writes aw = E/sum during load; scales out by 1/sum =
// 3-stage cp.async, one sync per iter; optional split-K via gridDim.z
__global__ void __launch_bounds__(256, 2) wm_av_norm(
    float* __restrict__ aw, const float* __restrict__ V,
    const float* __restrict__ part, float* __restrict__ outA,
    float* __restrict__ outB, int causal)
{
    extern __shared__ char sm[];
    float (*As)[128][24] = (float(*)[128][24])sm;            // 3 x 12288
    float (*Bs)[16][72]  = (float(*)[16][72])(sm + 36864);   // 3 x 4608
    float* invs          = (float*)(sm + 50688);             // 512
    float (*Os)[72]      = (float(*)[72])sm;                 // reuse: 36864

    const int bh = blockIdx.y;
    const int b = bh >> 3, h = bh & 7;
    const int i0 = blockIdx.x * 128;
    const int ks = blockIdx.z;
    const int t = threadIdx.x, wid = t >> 5, lane = t & 31;

    float* out = (ks == 0) ? outA : outB;
    float*       Abw = aw + (size_t)bh * Sq * Sq + (size_t)i0 * Sq;
    const float* Bb  = V + (size_t)b * Sq * Dm + h * DKh;
    float*       Cb  = out + (size_t)b * Sq * Dm + h * DKh;

    const int ktPer = 128 / gridDim.z;
    const int kt_lo = ks * ktPer;
    int kt_hi = kt_lo + ktPer;
    if (causal) { int ce = (i0 >> 4) + 8; if (ce < kt_hi) kt_hi = ce; }

    if (kt_hi <= kt_lo) {
        // no work: zero partial output region
        const float4 zero = make_float4(0.f, 0.f, 0.f, 0.f);
        for (int idx = t; idx < 2048; idx += 256) {
            int row = idx >> 4, c4 = idx & 15;
            *(float4*)&Cb[(size_t)(i0 + row) * Dm + c4 * 4] = zero;
        }
        return;
    }

    // per-row inverse softmax sums
    if (t < 128) {
        const float* pp = part + ((size_t)bh * Sq + i0 + t) * 16;
        float s = 0.f;
#pragma unroll
        for (int jt = 0; jt < 16; jt++) s += pp[jt];
        invs[t] = 1.f / s;
    }

    const int wm = (wid & 3) * 32, wn = (wid >> 2) * 32;
    wmma::fragment<wmma::accumulator, 16, 16, 8, float> acc[2][2];
#pragma unroll
    for (int i = 0; i < 2; i++)
#pragma unroll
        for (int j = 0; j < 2; j++) wmma::fill_fragment(acc[i][j], 0.f);

#define AV_LOAD(st, kt)                                                   \
    {                                                                     \
        _Pragma("unroll")                                                 \
        for (int c = t; c < 512; c += 256) {                              \
            int row = c >> 2, sg = c & 3;                                 \
            cp16(&As[st][row][sg*4],                                      \
                 Abw + (size_t)row * Sq + ((kt) << 4) + sg*4);            \
        }                                                                 \
        {                                                                 \
            int row = t >> 4, sg = t & 15;                                \
            cp16(&Bs[st][row][sg*4],                                      \
                 Bb + (size_t)(((kt) << 4) + row) * Dm + sg*4);           \
        }                                                                 \
        CP_COMMIT();                                                      \
    }

    AV_LOAD(0, kt_lo)
    if (kt_lo + 1 < kt_hi) AV_LOAD(1, kt_lo + 1)

    for (int kt = kt_lo; kt < kt_hi; kt++) {
        const int cur = (kt - kt_lo) % 3;
        if (kt + 1 < kt_hi) CP_WAIT1(); else CP_WAIT0();
        __syncthreads();
        if (kt + 2 < kt_hi) {
            int st = (kt - kt_lo + 2) % 3;
            AV_LOAD(st, kt + 2)
        }

        // write final normalized aw for this K-tile (reads raw E from smem)
        {
            int row = t >> 1, c0 = (t & 1) * 8;
            float inv = invs[row];
            float4 a0 = *(float4*)&As[cur][row][c0];
            float4 a1 = *(float4*)&As[cur][row][c0 + 4];
            a0.x *= inv; a0.y *= inv; a0.z *= inv; a0.w *= inv;
            a1.x *= inv; a1.y *= inv; a1.z *= inv; a1.w *= inv;
            float* aww = Abw + (size_t)row * Sq + (kt << 4) + c0;
            *(float4*)aww       = a0;
            *(float4*)(aww + 4) = a1;
        }

#pragma unroll
        for (int ksn = 0; ksn < 16; ksn += 8) {
            wmma::fragment<wmma::matrix_a, 16, 16, 8, wmma::precision::tf32,
                           wmma::row_major> af[2];
            wmma::fragment<wmma::matrix_b, 16, 16, 8, wmma::precision::tf32,
                           wmma::row_major> bf[2];
#pragma unroll
            for (int i = 0; i < 2; i++)
                wmma::load_matrix_sync(af[i], &As[cur][wm + i*16][ksn], 24);
#pragma unroll
            for (int j = 0; j < 2; j++)
                wmma::load_matrix_sync(bf[j], &Bs[cur][ksn][wn + j*16], 72);
#pragma unroll
            for (int i = 0; i < 2; i++)
#pragma unroll
                for (int j = 0; j < 2; j++)
                    wmma::mma_sync(acc[i][j], af[i], bf[j], acc[i][j]);
        }
    }
#undef AV_LOAD

    // epilogue: stage raw acc, then scale rows by 1/sum, coalesced write
    __syncthreads();
#pragma unroll
    for (int i = 0; i < 2; i++)
#pragma unroll
        for (int j = 0; j < 2; j++)
            wmma::store_matrix_sync(&Os[wm + i*16][wn + j*16], acc[i][j], 72,
                                    wmma::mem_row_major);
    __syncthreads();
#pragma unroll
    for (int r = 0; r < 16; r++) {
        const int row = wid * 16 + r;
        float2 v = *(float2*)&Os[row][lane * 2];
        const float inv = invs[row];
        v.x *= inv; v.y *= inv;
        *(float2*)&Cb[(size_t)(i0 + row) * Dm + lane * 2] = v;
    }
}

// ---------------- elementwise add (for split-K partials) --------------------
__global__ void __launch_bounds__(256) add2(
    float* __restrict__ a, const float* __restrict__ b)
{
    const size_t i = ((size_t)blockIdx.x * 256 + threadIdx.x) * 4;
    float4 va = *(float4*)&a[i];
    float4 vb = *(const float4*)&b[i];
    va.x += vb.x; va.y += vb.y; va.z += vb.z; va.w += vb.w;
    *(float4*)&a[i] = va;
}

// ---------------- residual add + layernorm over last dim (512) --------------
__global__ void __launch_bounds__(128) add_ln(
    const float* __restrict__ a, const float* __restrict__ r,
    const float* __restrict__ g, const float* __restrict__ be,
    float* __restrict__ out)
{
    const size_t row = blockIdx.x;
    const int t = threadIdx.x;
    __shared__ float red[4];

    float4 va = *(const float4*)&a[row * Dm + t*4];
    float4 vr = *(const float4*)&r[row * Dm + t*4];
    float x0 = va.x + vr.x, x1 = va.y + vr.y, x2 = va.z + vr.z, x3 = va.w + vr.w;

    float s = x0 + x1 + x2 + x3;
#pragma unroll
    for (int o = 16; o; o >>= 1) s += __shfl_xor_sync(0xffffffffu, s, o);
    if ((t & 31) == 0) red[t >> 5] = s;
    __syncthreads();
    float mean = (red[0] + red[1] + red[2] + red[3]) * (1.f / 512.f);

    float d0 = x0 - mean, d1 = x1 - mean, d2 = x2 - mean, d3 = x3 - mean;
    float vs = d0*d0 + d1*d1 + d2*d2 + d3*d3;
#pragma unroll
    for (int o = 16; o; o >>= 1) vs += __shfl_xor_sync(0xffffffffu, vs, o);
    __syncthreads();
    if ((t & 31) == 0) red[t >> 5] = vs;
    __syncthreads();
    float var = (red[0] + red[1] + red[2] + red[3]) * (1.f / 512.f);
    float rstd = rsqrtf(var + 1e-6f);

    float4 vg = *(const float4*)&g[t*4];
    float4 vb = *(const float4*)&be[t*4];
    float4 o4;
    o4.x = d0 * rstd * vg.x + vb.x;
    o4.y = d1 * rstd * vg.y + vb.y;
    o4.z = d2 * rstd * vg.z + vb.z;
    o4.w = d3 * rstd * vg.w + vb.w;
    *(float4*)&out[row * Dm + t*4] = o4;
}

// ---------------- launch ----------------------------------------------------
extern "C" void kernel_launch(void* const* d_in, const int* in_sizes, int n_in,
                              void* d_out, int out_size)
{
    const float* x    = (const float*)d_in[0];
    const float* enc  = (const float*)d_in[1];
    const float* wq1 = (const float*)d_in[3],  *bq1 = (const float*)d_in[4];
    const float* wk1 = (const float*)d_in[5],  *bk1 = (const float*)d_in[6];
    const float* wv1 = (const float*)d_in[7],  *bv1 = (const float*)d_in[8];
    const float* wo1 = (const float*)d_in[9],  *bo1 = (const float*)d_in[10];
    const float* wq2 = (const float*)d_in[11], *bq2 = (const float*)d_in[12];
    const float* wk2 = (const float*)d_in[13], *bk2 = (const float*)d_in[14];
    const float* wv2 = (const float*)d_in[15], *bv2 = (const float*)d_in[16];
    const float* wo2 = (const float*)d_in[17], *bo2 = (const float*)d_in[18];
    const float* wf1 = (const float*)d_in[19], *bf1 = (const float*)d_in[20];
    const float* wf2 = (const float*)d_in[21], *bf2 = (const float*)d_in[22];
    const float* g1 = (const float*)d_in[23], *be1 = (const float*)d_in[24];
    const float* g2 = (const float*)d_in[25], *be2 = (const float*)d_in[26];
    const float* g3 = (const float*)d_in[27], *be3 = (const float*)d_in[28];

    float* out3 = (float*)d_out;
    float* aw1  = out3 + (size_t)NB * Sq * Dm;
    float* aw2  = aw1  + (size_t)NB * NH * Sq * Sq;

    float *q, *k, *v, *t0, *t0b, *o1, *o2, *ffh, *part;
    cudaGetSymbolAddress((void**)&q,    g_q);
    cudaGetSymbolAddress((void**)&k,    g_k);
    cudaGetSymbolAddress((void**)&v,    g_v);
    cudaGetSymbolAddress((void**)&t0,   g_t0);
    cudaGetSymbolAddress((void**)&t0b,  g_t0b);
    cudaGetSymbolAddress((void**)&o1,   g_o1);
    cudaGetSymbolAddress((void**)&o2,   g_o2);
    cudaGetSymbolAddress((void**)&ffh,  g_ffh);
    cudaGetSymbolAddress((void**)&part, g_part);

    const int SMEM_GEMM  = 71680;
    const int SMEM_G64   = 53248;
    const int SMEM_LOG   = 69632;
    const int SMEM_AV    = 51200;
    cudaFuncSetAttribute(wm_gemm<false>, cudaFuncAttributeMaxDynamicSharedMemorySize, SMEM_GEMM);
    cudaFuncSetAttribute(wm_gemm<true>,  cudaFuncAttributeMaxDynamicSharedMemorySize, SMEM_GEMM);
    cudaFuncSetAttribute(wm_gemm3,       cudaFuncAttributeMaxDynamicSharedMemorySize, SMEM_GEMM);
    cudaFuncSetAttribute(wm_gemm64,      cudaFuncAttributeMaxDynamicSharedMemorySize, SMEM_G64);
    cudaFuncSetAttribute(wm_logits_exp,  cudaFuncAttributeMaxDynamicSharedMemorySize, SMEM_LOG);
    cudaFuncSetAttribute(wm_av_norm,     cudaFuncAttributeMaxDynamicSharedMemorySize, SMEM_AV);

    const dim3 gProj64(Dm / 128, MROWS / 64);       // (4, 64)
    const dim3 gQKV(12, MROWS / 128);               // (12, 32)
    const dim3 gFF1(FFd / 128, MROWS / 128);        // (16, 32)
    const dim3 gLog(Sq / 128, Sq / 128, NB * NH);   // (16, 16, 16)
    const dim3 gAV1(Sq / 128, NB * NH, 2);          // split-K causal
    const dim3 gAV2(Sq / 128, NB * NH, 1);
    const int  nAdd = (MROWS * Dm) / 4 / 256;       // 2048

    // ---- self attention ----
    wm_gemm3<<<gQKV, 256, SMEM_GEMM>>>(x, x, x, wq1, wk1, wv1,
                                       bq1, bk1, bv1, q, k, v, Dm, Dm);
    wm_logits_exp<<<gLog, 256, SMEM_LOG>>>(q, k, aw1, part, 1);
    wm_av_norm<<<gAV1, 256, SMEM_AV>>>(aw1, v, part, t0, t0b, 1);
    add2<<<nAdd, 256>>>(t0, t0b);
    wm_gemm64<<<gProj64, 256, SMEM_G64>>>(t0, wo1, bo1, q, Dm, Dm);
    add_ln<<<MROWS, 128>>>(q, x, g1, be1, o1);

    // ---- cross attention ----
    wm_gemm3<<<gQKV, 256, SMEM_GEMM>>>(o1, enc, enc, wq2, wk2, wv2,
                                       bq2, bk2, bv2, q, k, v, Dm, Dm);
    wm_logits_exp<<<gLog, 256, SMEM_LOG>>>(q, k, aw2, part, 0);
    wm_av_norm<<<gAV2, 256, SMEM_AV>>>(aw2, v, part, t0, t0b, 0);
    wm_gemm64<<<gProj64, 256, SMEM_G64>>>(t0, wo2, bo2, q, Dm, Dm);
    add_ln<<<MROWS, 128>>>(q, o1, g2, be2, o2);

    // ---- FFN ----
    wm_gemm<true ><<<gFF1, 256, SMEM_GEMM>>>(o2, wf1, bf1, ffh, FFd, Dm);
    wm_gemm64<<<gProj64, 256, SMEM_G64>>>(ffh, wf2, bf2, t0, Dm, FFd);
    add_ln<<<MROWS, 128>>>(t0, o2, g3, be3, out3);
}

// round 11
// speedup vs baseline: 1.0055x; 1.0035x over previous
#include <cuda_runtime.h>
#include <math.h>
#include <stdint.h>
#include <mma.h>

using namespace nvcuda;

// Problem constants
#define Sq   2048
#define Dm   512
#define NH   8
#define DKh  64
#define NB   2
#define FFd  2048
#define MROWS (NB*Sq)   // 4096

// ---------------- scratch (static device globals; no allocs) ----------------
__device__ float g_q  [MROWS*Dm];
__device__ float g_k  [MROWS*Dm];
__device__ float g_v  [MROWS*Dm];
__device__ float g_t0 [MROWS*Dm];
__device__ float g_t0b[MROWS*Dm];
__device__ float g_o1 [MROWS*Dm];
__device__ float g_o2 [MROWS*Dm];
__device__ float g_ffh[MROWS*FFd];
__device__ float g_part[(size_t)NB*NH*Sq*16];   // row partial sums (2MB)

// ---------------- cp.async helpers ------------------------------------------
__device__ __forceinline__ void cp16(const void* dst, const void* src) {
    uint32_t d = (uint32_t)__cvta_generic_to_shared(dst);
    asm volatile("cp.async.cg.shared.global [%0], [%1], 16;" :: "r"(d), "l"(src));
}
#define CP_COMMIT() asm volatile("cp.async.commit_group;" ::: "memory")
#define CP_WAIT1()  asm volatile("cp.async.wait_group 1;" ::: "memory")
#define CP_WAIT0()  asm volatile("cp.async.wait_group 0;" ::: "memory")

// =============== shared GEMM body: C = A[.,K] @ B[K,N] + bias ================
// BM=128, BN=128, BK=16, 3-stage cp.async, ONE sync per K-iter, 256 threads
__device__ __forceinline__ void gemm_body(
    const float* __restrict__ A, const float* __restrict__ B,
    const float* __restrict__ bias, float* __restrict__ C,
    int N, int K, int m0, int n0, bool relu, char* sm)
{
    float (*As)[128][24] = (float(*)[128][24])sm;                 // 3 x 12288
    float (*Bs)[16][136] = (float(*)[16][136])(sm + 36864);       // 3 x 8704
    float (*BiasS)[136]  = (float(*)[136])(sm + 62976);           // 8704

    const int t = threadIdx.x, wid = t >> 5;
    const int wm = (wid & 3) * 32, wn = (wid >> 2) * 64;

    {
        int col = t & 127, r0 = (t >> 7) * 8;
        float bv = bias[n0 + col];
#pragma unroll
        for (int r = 0; r < 8; r++) BiasS[r0 + r][col] = bv;
    }
    __syncthreads();

    wmma::fragment<wmma::accumulator, 16, 16, 8, float> acc[2][4];
#pragma unroll
    for (int i = 0; i < 2; i++)
#pragma unroll
        for (int j = 0; j < 4; j++)
            wmma::load_matrix_sync(acc[i][j], &BiasS[0][wn + j*16], 136,
                                   wmma::mem_row_major);

    const float* Ab = A + (size_t)m0 * K;
    const float* Bb = B + n0;

#define G_LOAD(st, k0)                                                    \
    {                                                                     \
        _Pragma("unroll")                                                 \
        for (int c = t; c < 512; c += 256) {                              \
            int row = c >> 2, sg = c & 3;                                 \
            cp16(&As[st][row][sg*4], Ab + (size_t)row * K + (k0) + sg*4); \
        }                                                                 \
        _Pragma("unroll")                                                 \
        for (int c = t; c < 512; c += 256) {                              \
            int row = c >> 5, sg = c & 31;                                \
            cp16(&Bs[st][row][sg*4], Bb + (size_t)((k0) + row) * N + sg*4); \
        }                                                                 \
        CP_COMMIT();                                                      \
    }

    G_LOAD(0, 0)
    G_LOAD(1, 16)

    const int KT = K >> 4;
    for (int kt = 0; kt < KT; kt++) {
        const int cur = kt % 3;
        if (kt + 1 < KT) CP_WAIT1(); else CP_WAIT0();
        __syncthreads();
        if (kt + 2 < KT) { int st = (kt + 2) % 3; G_LOAD(st, (kt + 2) << 4) }
#pragma unroll
        for (int ks = 0; ks < 16; ks += 8) {
            wmma::fragment<wmma::matrix_a, 16, 16, 8, wmma::precision::tf32,
                           wmma::row_major> af[2];
            wmma::fragment<wmma::matrix_b, 16, 16, 8, wmma::precision::tf32,
                           wmma::row_major> bf[4];
#pragma unroll
            for (int i = 0; i < 2; i++)
                wmma::load_matrix_sync(af[i], &As[cur][wm + i*16][ks], 24);
#pragma unroll
            for (int j = 0; j < 4; j++)
                wmma::load_matrix_sync(bf[j], &Bs[cur][ks][wn + j*16], 136);
#pragma unroll
            for (int i = 0; i < 2; i++)
#pragma unroll
                for (int j = 0; j < 4; j++)
                    wmma::mma_sync(acc[i][j], af[i], bf[j], acc[i][j]);
        }
    }
#undef G_LOAD

#pragma unroll
    for (int i = 0; i < 2; i++)
#pragma unroll
        for (int j = 0; j < 4; j++) {
            if (relu) {
#pragma unroll
                for (int e = 0; e < acc[i][j].num_elements; e++)
                    acc[i][j].x[e] = fmaxf(acc[i][j].x[e], 0.f);
            }
            wmma::store_matrix_sync(
                &C[(size_t)(m0 + wm + i*16) * N + n0 + wn + j*16],
                acc[i][j], N, wmma::mem_row_major);
        }
}

template<bool RELU>
__global__ void __launch_bounds__(256, 2) wm_gemm(
    const float* __restrict__ A, const float* __restrict__ B,
    const float* __restrict__ bias, float* __restrict__ C, int N, int K)
{
    extern __shared__ char sm[];
    gemm_body(A, B, bias, C, N, K, blockIdx.y * 128, blockIdx.x * 128, RELU, sm);
}

// fused triple GEMM (shares grid across 3 weight matrices, N=512 each)
__global__ void __launch_bounds__(256, 2) wm_gemm3(
    const float* __restrict__ A0, const float* __restrict__ A1,
    const float* __restrict__ A2,
    const float* __restrict__ B0, const float* __restrict__ B1,
    const float* __restrict__ B2,
    const float* __restrict__ b0, const float* __restrict__ b1,
    const float* __restrict__ b2,
    float* __restrict__ C0, float* __restrict__ C1, float* __restrict__ C2,
    int N, int K)
{
    extern __shared__ char sm[];
    const int mat = blockIdx.x >> 2;
    const float* A = (mat == 0) ? A0 : (mat == 1) ? A1 : A2;
    const float* B = (mat == 0) ? B0 : (mat == 1) ? B1 : B2;
    const float* bias = (mat == 0) ? b0 : (mat == 1) ? b1 : b2;
    float* C = (mat == 0) ? C0 : (mat == 1) ? C1 : C2;
    gemm_body(A, B, bias, C, N, K, blockIdx.y * 128, (blockIdx.x & 3) * 128,
              false, sm);
}

// =============== BM=64 GEMM for underfilled shapes (wo, ff2) ================
__global__ void __launch_bounds__(256, 2) wm_gemm64(
    const float* __restrict__ A, const float* __restrict__ B,
    const float* __restrict__ bias, float* __restrict__ C, int N, int K)
{
    extern __shared__ char sm[];
    float (*As)[64][24]  = (float(*)[64][24])sm;                  // 3 x 6144
    float (*Bs)[16][136] = (float(*)[16][136])(sm + 18432);       // 3 x 8704
    float (*BiasS)[136]  = (float(*)[136])(sm + 44544);           // 8704

    const int t = threadIdx.x, wid = t >> 5;
    const int m0 = blockIdx.y * 64, n0 = blockIdx.x * 128;
    const int wm = (wid & 3) * 16, wn = (wid >> 2) * 64;

    {
        int col = t & 127, r0 = (t >> 7) * 8;
        float bv = bias[n0 + col];
#pragma unroll
        for (int r = 0; r < 8; r++) BiasS[r0 + r][col] = bv;
    }
    __syncthreads();

    wmma::fragment<wmma::accumulator, 16, 16, 8, float> acc[4];
#pragma unroll
    for (int j = 0; j < 4; j++)
        wmma::load_matrix_sync(acc[j], &BiasS[0][wn + j*16], 136,
                               wmma::mem_row_major);

    const float* Ab = A + (size_t)m0 * K;
    const float* Bb = B + n0;

#define G64_LOAD(st, k0)                                                  \
    {                                                                     \
        int row = t >> 2, sg = t & 3;                                     \
        cp16(&As[st][row][sg*4], Ab + (size_t)row * K + (k0) + sg*4);     \
        _Pragma("unroll")                                                 \
        for (int c = t; c < 512; c += 256) {                              \
            int r2 = c >> 5, s2 = c & 31;                                 \
            cp16(&Bs[st][r2][s2*4], Bb + (size_t)((k0) + r2) * N + s2*4); \
        }                                                                 \
        CP_COMMIT();                                                      \
    }

    G64_LOAD(0, 0)
    G64_LOAD(1, 16)

    const int KT = K >> 4;
    for (int kt = 0; kt < KT; kt++) {
        const int cur = kt % 3;
        if (kt + 1 < KT) CP_WAIT1(); else CP_WAIT0();
        __syncthreads();
        if (kt + 2 < KT) { int st = (kt + 2) % 3; G64_LOAD(st, (kt + 2) << 4) }
#pragma unroll
        for (int ks = 0; ks < 16; ks += 8) {
            wmma::fragment<wmma::matrix_a, 16, 16, 8, wmma::precision::tf32,
                           wmma::row_major> af;
            wmma::fragment<wmma::matrix_b, 16, 16, 8, wmma::precision::tf32,
                           wmma::row_major> bf[4];
            wmma::load_matrix_sync(af, &As[cur][wm][ks], 24);
#pragma unroll
            for (int j = 0; j < 4; j++)
                wmma::load_matrix_sync(bf[j], &Bs[cur][ks][wn + j*16], 136);
#pragma unroll
            for (int j = 0; j < 4; j++)
                wmma::mma_sync(acc[j], af, bf[j], acc[j]);
        }
    }
#undef G64_LOAD

#pragma unroll
    for (int j = 0; j < 4; j++)
        wmma::store_matrix_sync(&C[(size_t)(m0 + wm) * N + n0 + wn + j*16],
                                acc[j], N, wmma::mem_row_major);
}

// ===== logits+exp: E = exp(scale*Q@K^T) (masked->0) + row partial sums ======
__global__ void __launch_bounds__(256, 2) wm_logits_exp(
    const float* __restrict__ Q, const float* __restrict__ Km,
    float* __restrict__ out, float* __restrict__ part, int causal)
{
    extern __shared__ char smc[];
    float (*Qs)[68] = (float(*)[68])smc;                 // 34816
    float (*Ks)[68] = (float(*)[68])(smc + 34816);       // 34816
    float (*St)[136] = (float(*)[136])smc;               // reuse: 69632

    const int bh = blockIdx.z;
    const int b = bh >> 3, h = bh & 7;
    const int i0 = blockIdx.y * 128, j0 = blockIdx.x * 128;
    const int jt = blockIdx.x;
    const int t = threadIdx.x, wid = t >> 5, lane = t & 31;
    float* Ob = out + (size_t)bh * Sq * Sq;

    if (causal && j0 > i0 + 127) {
        const float4 zero = make_float4(0.f, 0.f, 0.f, 0.f);
        for (int idx = t; idx < 4096; idx += 256) {
            int row = idx >> 5, c4 = idx & 31;
            *(float4*)&Ob[(size_t)(i0 + row) * Sq + j0 + c4 * 4] = zero;
        }
        if (t < 128)
            part[((size_t)bh * Sq + i0 + t) * 16 + jt] = 0.f;
        return;
    }

    const float* Qb = Q  + (size_t)b * Sq * Dm + h * DKh + (size_t)i0 * Dm;
    const float* Kb = Km + (size_t)b * Sq * Dm + h * DKh + (size_t)j0 * Dm;

#pragma unroll
    for (int c = t; c < 2048; c += 256) {
        int row = c >> 4, sg = c & 15;
        cp16(&Qs[row][sg*4], Qb + (size_t)row * Dm + sg*4);
    }
#pragma unroll
    for (int c = t; c < 2048; c += 256) {
        int row = c >> 4, sg = c & 15;
        cp16(&Ks[row][sg*4], Kb + (size_t)row * Dm + sg*4);
    }
    CP_COMMIT();
    CP_WAIT0();
    __syncthreads();

    const int wm = (wid & 3) * 32, wn = (wid >> 2) * 64;
    wmma::fragment<wmma::accumulator, 16, 16, 8, float> acc[2][4];
#pragma unroll
    for (int i = 0; i < 2; i++)
#pragma unroll
        for (int j = 0; j < 4; j++) wmma::fill_fragment(acc[i][j], 0.f);

#pragma unroll
    for (int ks = 0; ks < 64; ks += 8) {
        wmma::fragment<wmma::matrix_a, 16, 16, 8, wmma::precision::tf32,
                       wmma::row_major> af[2];
        wmma::fragment<wmma::matrix_b, 16, 16, 8, wmma::precision::tf32,
                       wmma::col_major> bf[4];
#pragma unroll
        for (int i = 0; i < 2; i++)
            wmma::load_matrix_sync(af[i], &Qs[wm + i*16][ks], 68);
#pragma unroll
        for (int j = 0; j < 4; j++)
            wmma::load_matrix_sync(bf[j], &Ks[wn + j*16][ks], 68);
#pragma unroll
        for (int i = 0; i < 2; i++)
#pragma unroll
            for (int j = 0; j < 4; j++)
                wmma::mma_sync(acc[i][j], af[i], bf[j], acc[i][j]);
    }
    __syncthreads();   // done with Qs/Ks; reuse as staging

#pragma unroll
    for (int i = 0; i < 2; i++)
#pragma unroll
        for (int j = 0; j < 4; j++)
            wmma::store_matrix_sync(&St[wm + i*16][wn + j*16], acc[i][j], 136,
                                    wmma::mem_row_major);
    __syncthreads();

    // epilogue: warp-per-row, fully coalesced 512B writes
    const int gjl = j0 + lane * 4;
#pragma unroll
    for (int r = 0; r < 16; r++) {
        const int row = wid * 16 + r;
        const int gi = i0 + row;
        float4 v = *(float4*)&St[row][lane * 4];
        v.x = (causal && gjl + 0 > gi) ? 0.f : __expf(v.x * 0.125f);
        v.y = (causal && gjl + 1 > gi) ? 0.f : __expf(v.y * 0.125f);
        v.z = (causal && gjl + 2 > gi) ? 0.f : __expf(v.z * 0.125f);
        v.w = (causal && gjl + 3 > gi) ? 0.f : __expf(v.w * 0.125f);
        float psum = v.x + v.y + v.z + v.w;
#pragma unroll
        for (int o = 16; o; o >>= 1)
            psum += __shfl_xor_sync(0xffffffffu, psum, o);
        *(float4*)&Ob[(size_t)gi * Sq + j0 + lane * 4] = v;
        if (lane == 0)
            part[((size_t)bh * Sq + gi) * 16 + jt] = psum;
    }
}

// ===== AV: MMA on raw E; writes aw = E/sum during load; scales out by 1/sum =
// 3-stage cp.async, one sync per iter; optional split-K via gridDim.z
__global__ void __launch_bounds__(256, 2) wm_av_norm(
    float* __restrict__ aw, const float* __restrict__ V,
    const float* __restrict__ part, float* __restrict__ outA,
    float* __restrict__ outB, int causal)
{
    extern __shared__ char sm[];
    float (*As)[128][24] = (float(*)[128][24])sm;            // 3 x 12288
    float (*Bs)[16][72]  = (float(*)[16][72])(sm + 36864);   // 3 x 4608
    float* invs          = (float*)(sm + 50688);             // 512
    float (*Os)[72]      = (float(*)[72])sm;                 // reuse: 36864

    const int bh = blockIdx.y;
    const int b = bh >> 3, h = bh & 7;
    const int i0 = blockIdx.x * 128;
    const int ks = blockIdx.z;
    const int t = threadIdx.x, wid = t >> 5, lane = t & 31;

    float* out = (ks == 0) ? outA : outB;
    float*       Abw = aw + (size_t)bh * Sq * Sq + (size_t)i0 * Sq;
    const float* Bb  = V + (size_t)b * Sq * Dm + h * DKh;
    float*       Cb  = out + (size_t)b * Sq * Dm + h * DKh;

    const int ktPer = 128 / gridDim.z;
    const int kt_lo = ks * ktPer;
    int kt_hi = kt_lo + ktPer;
    if (causal) { int ce = (i0 >> 4) + 8; if (ce < kt_hi) kt_hi = ce; }

    if (kt_hi <= kt_lo) {
        // no work: zero partial output region
        const float4 zero = make_float4(0.f, 0.f, 0.f, 0.f);
        for (int idx = t; idx < 2048; idx += 256) {
            int row = idx >> 4, c4 = idx & 15;
            *(float4*)&Cb[(size_t)(i0 + row) * Dm + c4 * 4] = zero;
        }
        return;
    }

    // per-row inverse softmax sums
    if (t < 128) {
        const float* pp = part + ((size_t)bh * Sq + i0 + t) * 16;
        float s = 0.f;
#pragma unroll
        for (int jt = 0; jt < 16; jt++) s += pp[jt];
        invs[t] = 1.f / s;
    }

    const int wm = (wid & 3) * 32, wn = (wid >> 2) * 32;
    wmma::fragment<wmma::accumulator, 16, 16, 8, float> acc[2][2];
#pragma unroll
    for (int i = 0; i < 2; i++)
#pragma unroll
        for (int j = 0; j < 2; j++) wmma::fill_fragment(acc[i][j], 0.f);

#define AV_LOAD(st, kt)                                                   \
    {                                                                     \
        _Pragma("unroll")                                                 \
        for (int c = t; c < 512; c += 256) {                              \
            int row = c >> 2, sg = c & 3;                                 \
            cp16(&As[st][row][sg*4],                                      \
                 Abw + (size_t)row * Sq + ((kt) << 4) + sg*4);            \
        }                                                                 \
        {                                                                 \
            int row = t >> 4, sg = t & 15;                                \
            cp16(&Bs[st][row][sg*4],                                      \
                 Bb + (size_t)(((kt) << 4) + row) * Dm + sg*4);           \
        }                                                                 \
        CP_COMMIT();                                                      \
    }

    AV_LOAD(0, kt_lo)
    if (kt_lo + 1 < kt_hi) AV_LOAD(1, kt_lo + 1)

    for (int kt = kt_lo; kt < kt_hi; kt++) {
        const int cur = (kt - kt_lo) % 3;
        if (kt + 1 < kt_hi) CP_WAIT1(); else CP_WAIT0();
        __syncthreads();
        if (kt + 2 < kt_hi) {
            int st = (kt - kt_lo + 2) % 3;
            AV_LOAD(st, kt + 2)
        }

        // write final normalized aw for this K-tile (reads raw E from smem)
        {
            int row = t >> 1, c0 = (t & 1) * 8;
            float inv = invs[row];
            float4 a0 = *(float4*)&As[cur][row][c0];
            float4 a1 = *(float4*)&As[cur][row][c0 + 4];
            a0.x *= inv; a0.y *= inv; a0.z *= inv; a0.w *= inv;
            a1.x *= inv; a1.y *= inv; a1.z *= inv; a1.w *= inv;
            float* aww = Abw + (size_t)row * Sq + (kt << 4) + c0;
            *(float4*)aww       = a0;
            *(float4*)(aww + 4) = a1;
        }

#pragma unroll
        for (int ksn = 0; ksn < 16; ksn += 8) {
            wmma::fragment<wmma::matrix_a, 16, 16, 8, wmma::precision::tf32,
                           wmma::row_major> af[2];
            wmma::fragment<wmma::matrix_b, 16, 16, 8, wmma::precision::tf32,
                           wmma::row_major> bf[2];
#pragma unroll
            for (int i = 0; i < 2; i++)
                wmma::load_matrix_sync(af[i], &As[cur][wm + i*16][ksn], 24);
#pragma unroll
            for (int j = 0; j < 2; j++)
                wmma::load_matrix_sync(bf[j], &Bs[cur][ksn][wn + j*16], 72);
#pragma unroll
            for (int i = 0; i < 2; i++)
#pragma unroll
                for (int j = 0; j < 2; j++)
                    wmma::mma_sync(acc[i][j], af[i], bf[j], acc[i][j]);
        }
    }
#undef AV_LOAD

    // epilogue: stage raw acc, then scale rows by 1/sum, coalesced write
    __syncthreads();
#pragma unroll
    for (int i = 0; i < 2; i++)
#pragma unroll
        for (int j = 0; j < 2; j++)
            wmma::store_matrix_sync(&Os[wm + i*16][wn + j*16], acc[i][j], 72,
                                    wmma::mem_row_major);
    __syncthreads();
#pragma unroll
    for (int r = 0; r < 16; r++) {
        const int row = wid * 16 + r;
        float2 v = *(float2*)&Os[row][lane * 2];
        const float inv = invs[row];
        v.x *= inv; v.y *= inv;
        *(float2*)&Cb[(size_t)(i0 + row) * Dm + lane * 2] = v;
    }
}

// ---------------- elementwise add (for split-K partials) --------------------
__global__ void __launch_bounds__(256) add2(
    float* __restrict__ a, const float* __restrict__ b)
{
    const size_t i = ((size_t)blockIdx.x * 256 + threadIdx.x) * 4;
    float4 va = *(float4*)&a[i];
    float4 vb = *(const float4*)&b[i];
    va.x += vb.x; va.y += vb.y; va.z += vb.z; va.w += vb.w;
    *(float4*)&a[i] = va;
}

// ---------------- residual add + layernorm over last dim (512) --------------
__global__ void __launch_bounds__(128) add_ln(
    const float* __restrict__ a, const float* __restrict__ r,
    const float* __restrict__ g, const float* __restrict__ be,
    float* __restrict__ out)
{
    const size_t row = blockIdx.x;
    const int t = threadIdx.x;
    __shared__ float red[4];

    float4 va = *(const float4*)&a[row * Dm + t*4];
    float4 vr = *(const float4*)&r[row * Dm + t*4];
    float x0 = va.x + vr.x, x1 = va.y + vr.y, x2 = va.z + vr.z, x3 = va.w + vr.w;

    float s = x0 + x1 + x2 + x3;
#pragma unroll
    for (int o = 16; o; o >>= 1) s += __shfl_xor_sync(0xffffffffu, s, o);
    if ((t & 31) == 0) red[t >> 5] = s;
    __syncthreads();
    float mean = (red[0] + red[1] + red[2] + red[3]) * (1.f / 512.f);

    float d0 = x0 - mean, d1 = x1 - mean, d2 = x2 - mean, d3 = x3 - mean;
    float vs = d0*d0 + d1*d1 + d2*d2 + d3*d3;
#pragma unroll
    for (int o = 16; o; o >>= 1) vs += __shfl_xor_sync(0xffffffffu, vs, o);
    __syncthreads();
    if ((t & 31) == 0) red[t >> 5] = vs;
    __syncthreads();
    float var = (red[0] + red[1] + red[2] + red[3]) * (1.f / 512.f);
    float rstd = rsqrtf(var + 1e-6f);

    float4 vg = *(const float4*)&g[t*4];
    float4 vb = *(const float4*)&be[t*4];
    float4 o4;
    o4.x = d0 * rstd * vg.x + vb.x;
    o4.y = d1 * rstd * vg.y + vb.y;
    o4.z = d2 * rstd * vg.z + vb.z;
    o4.w = d3 * rstd * vg.w + vb.w;
    *(float4*)&out[row * Dm + t*4] = o4;
}

// ---------------- launch ----------------------------------------------------
extern "C" void kernel_launch(void* const* d_in, const int* in_sizes, int n_in,
                              void* d_out, int out_size)
{
    const float* x    = (const float*)d_in[0];
    const float* enc  = (const float*)d_in[1];
    const float* wq1 = (const float*)d_in[3],  *bq1 = (const float*)d_in[4];
    const float* wk1 = (const float*)d_in[5],  *bk1 = (const float*)d_in[6];
    const float* wv1 = (const float*)d_in[7],  *bv1 = (const float*)d_in[8];
    const float* wo1 = (const float*)d_in[9],  *bo1 = (const float*)d_in[10];
    const float* wq2 = (const float*)d_in[11], *bq2 = (const float*)d_in[12];
    const float* wk2 = (const float*)d_in[13], *bk2 = (const float*)d_in[14];
    const float* wv2 = (const float*)d_in[15], *bv2 = (const float*)d_in[16];
    const float* wo2 = (const float*)d_in[17], *bo2 = (const float*)d_in[18];
    const float* wf1 = (const float*)d_in[19], *bf1 = (const float*)d_in[20];
    const float* wf2 = (const float*)d_in[21], *bf2 = (const float*)d_in[22];
    const float* g1 = (const float*)d_in[23], *be1 = (const float*)d_in[24];
    const float* g2 = (const float*)d_in[25], *be2 = (const float*)d_in[26];
    const float* g3 = (const float*)d_in[27], *be3 = (const float*)d_in[28];

    float* out3 = (float*)d_out;
    float* aw1  = out3 + (size_t)NB * Sq * Dm;
    float* aw2  = aw1  + (size_t)NB * NH * Sq * Sq;

    float *q, *k, *v, *t0, *t0b, *o1, *o2, *ffh, *part;
    cudaGetSymbolAddress((void**)&q,    g_q);
    cudaGetSymbolAddress((void**)&k,    g_k);
    cudaGetSymbolAddress((void**)&v,    g_v);
    cudaGetSymbolAddress((void**)&t0,   g_t0);
    cudaGetSymbolAddress((void**)&t0b,  g_t0b);
    cudaGetSymbolAddress((void**)&o1,   g_o1);
    cudaGetSymbolAddress((void**)&o2,   g_o2);
    cudaGetSymbolAddress((void**)&ffh,  g_ffh);
    cudaGetSymbolAddress((void**)&part, g_part);

    const int SMEM_GEMM  = 71680;
    const int SMEM_G64   = 53248;
    const int SMEM_LOG   = 69632;
    const int SMEM_AV    = 51200;
    cudaFuncSetAttribute(wm_gemm<false>, cudaFuncAttributeMaxDynamicSharedMemorySize, SMEM_GEMM);
    cudaFuncSetAttribute(wm_gemm<true>,  cudaFuncAttributeMaxDynamicSharedMemorySize, SMEM_GEMM);
    cudaFuncSetAttribute(wm_gemm3,       cudaFuncAttributeMaxDynamicSharedMemorySize, SMEM_GEMM);
    cudaFuncSetAttribute(wm_gemm64,      cudaFuncAttributeMaxDynamicSharedMemorySize, SMEM_G64);
    cudaFuncSetAttribute(wm_logits_exp,  cudaFuncAttributeMaxDynamicSharedMemorySize, SMEM_LOG);
    cudaFuncSetAttribute(wm_av_norm,     cudaFuncAttributeMaxDynamicSharedMemorySize, SMEM_AV);

    const dim3 gProj64(Dm / 128, MROWS / 64);       // (4, 64)
    const dim3 gQKV(12, MROWS / 128);               // (12, 32)
    const dim3 gFF1(FFd / 128, MROWS / 128);        // (16, 32)
    const dim3 gLog(Sq / 128, Sq / 128, NB * NH);   // (16, 16, 16)
    const dim3 gAV1(Sq / 128, NB * NH, 2);          // split-K causal
    const dim3 gAV2(Sq / 128, NB * NH, 1);
    const int  nAdd = (MROWS * Dm) / 4 / 256;       // 2048

    // ---- self attention ----
    wm_gemm3<<<gQKV, 256, SMEM_GEMM>>>(x, x, x, wq1, wk1, wv1,
                                       bq1, bk1, bv1, q, k, v, Dm, Dm);
    wm_logits_exp<<<gLog, 256, SMEM_LOG>>>(q, k, aw1, part, 1);
    wm_av_norm<<<gAV1, 256, SMEM_AV>>>(aw1, v, part, t0, t0b, 1);
    add2<<<nAdd, 256>>>(t0, t0b);
    wm_gemm64<<<gProj64, 256, SMEM_G64>>>(t0, wo1, bo1, q, Dm, Dm);
    add_ln<<<MROWS, 128>>>(q, x, g1, be1, o1);

    // ---- cross attention ----
    wm_gemm3<<<gQKV, 256, SMEM_GEMM>>>(o1, enc, enc, wq2, wk2, wv2,
                                       bq2, bk2, bv2, q, k, v, Dm, Dm);
    wm_logits_exp<<<gLog, 256, SMEM_LOG>>>(q, k, aw2, part, 0);
    wm_av_norm<<<gAV2, 256, SMEM_AV>>>(aw2, v, part, t0, t0b, 0);
    wm_gemm64<<<gProj64, 256, SMEM_G64>>>(t0, wo2, bo2, q, Dm, Dm);
    add_ln<<<MROWS, 128>>>(q, o1, g2, be2, o2);

    // ---- FFN ----
    wm_gemm<true ><<<gFF1, 256, SMEM_GEMM>>>(o2, wf1, bf1, ffh, FFd, Dm);
    wm_gemm64<<<gProj64, 256, SMEM_G64>>>(ffh, wf2, bf2, t0, Dm, FFd);
    add_ln<<<MROWS, 128>>>(t0, o2, g3, be3, out3);
}